// round 11
// baseline (speedup 1.0000x reference)
#include <cuda_runtime.h>
#include <cuda_fp16.h>

#define NMAX 100000
#define EMAX 3200000
#define DD 64
#define SCAN_B 1024
#define NBMAX ((NMAX + SCAN_B - 1) / SCAN_B + 1)

// Scratch (device globals; allocation is forbidden)
// Layer-1 CSR set
__device__ float  g_dinv[NMAX];
__device__ int    g_cnt[NMAX];
__device__ int    g_off[NMAX];
__device__ int    g_cur[NMAX];
__device__ int    g_bsum[NBMAX];
__device__ int    g_csr[EMAX];
// Layer-2 CSR set (built concurrently on a forked stream)
__device__ float  g_dinv2[NMAX];
__device__ int    g_cnt2[NMAX];
__device__ int    g_off2[NMAX];
__device__ int    g_cur2[NMAX];
__device__ int    g_bsum2[NBMAX];
__device__ int    g_csr2[EMAX];

__device__ __half2 g_hsh[NMAX * 32];   // (X@W)*dinv[row], fp16, 32 half2 per row
__device__ float  g_agg[NMAX * DD];    // layer-1 output (self+bias, then += messages)

// ---------------------------------------------------------------------------
// CSR build: count -> scan -> fill.  (deg = cnt + 1 gives dinv for free)
__global__ void k_count(const int* __restrict__ dst, int* __restrict__ cnt, int ne) {
    int i = blockIdx.x * blockDim.x + threadIdx.x;
    if (i < ne) atomicAdd(cnt + dst[i], 1);   // no return -> RED
}

__global__ void k_scan1(const int* __restrict__ cnt, int* __restrict__ off,
                        int* __restrict__ bsum, int n) {
    __shared__ int sh[SCAN_B];
    int i = blockIdx.x * SCAN_B + threadIdx.x;
    int v = (i < n) ? cnt[i] : 0;
    sh[threadIdx.x] = v;
    __syncthreads();
#pragma unroll
    for (int d = 1; d < SCAN_B; d <<= 1) {
        int t = (threadIdx.x >= d) ? sh[threadIdx.x - d] : 0;
        __syncthreads();
        sh[threadIdx.x] += t;
        __syncthreads();
    }
    if (i < n) off[i] = sh[threadIdx.x] - v;          // exclusive within block
    if (threadIdx.x == SCAN_B - 1) bsum[blockIdx.x] = sh[SCAN_B - 1];
}

__global__ void k_scan2(int* bsum, int nb) {
    if (blockIdx.x == 0 && threadIdx.x == 0) {
        int run = 0;
        for (int b = 0; b < nb; b++) { int t = bsum[b]; bsum[b] = run; run += t; }
    }
}

__global__ void k_scan3(int* __restrict__ off, const int* __restrict__ bsum,
                        int* __restrict__ cur, const int* __restrict__ cnt,
                        float* __restrict__ dinv, int n) {
    int i = blockIdx.x * blockDim.x + threadIdx.x;
    if (i >= n) return;
    int o = off[i] + bsum[i / SCAN_B];
    off[i] = o;
    cur[i] = o;
    dinv[i] = rsqrtf((float)cnt[i] + 1.0f);
}

__global__ void k_fill(const int* __restrict__ src, const int* __restrict__ dst,
                       int* __restrict__ cur, int* __restrict__ csr, int ne) {
    int i = blockIdx.x * blockDim.x + threadIdx.x;
    if (i < ne) {
        int p = atomicAdd(cur + dst[i], 1);
        csr[p] = src[i];
    }
}

// ---------------------------------------------------------------------------
// Register-tiled GEMM + fused epilogue.
//   h   = f(in) @ W        (f = identity or ReLU)
//   hsh = fp16(h * dinv[row])          -> message features for gather
//   agg = h * dinv^2 + b   (fp32)      -> self-loop + bias (output init)
#define XPAD 68
__global__ __launch_bounds__(256, 2)
void k_gemm_fused(const float* __restrict__ in, const float* __restrict__ W,
                  const float* __restrict__ b, const float* __restrict__ dinv,
                  __half2* __restrict__ hsh, float* __restrict__ agg,
                  int n, int do_relu) {
    extern __shared__ float smem_f[];
    float* Ws = smem_f;                 // 64*64
    float* xs = smem_f + DD * DD;       // 256*XPAD

    int tid = threadIdx.x;
    int cx = tid & 15;
    int ry = tid >> 4;
    int row0 = blockIdx.x * 256;

    for (int i = tid; i < DD * DD; i += 256) Ws[i] = W[i];

    for (int i = tid; i < 256 * 16; i += 256) {
        int r = i >> 4, c4 = i & 15;
        int grow = row0 + r;
        float4 v = make_float4(0.f, 0.f, 0.f, 0.f);
        if (grow < n) v = __ldg(reinterpret_cast<const float4*>(in + (size_t)grow * DD) + c4);
        if (do_relu) {
            v.x = fmaxf(v.x, 0.f); v.y = fmaxf(v.y, 0.f);
            v.z = fmaxf(v.z, 0.f); v.w = fmaxf(v.w, 0.f);
        }
        *reinterpret_cast<float4*>(&xs[r * XPAD + c4 * 4]) = v;
    }
    __syncthreads();

    float4 acc[16];
#pragma unroll
    for (int i = 0; i < 16; i++) acc[i] = make_float4(0.f, 0.f, 0.f, 0.f);

#pragma unroll
    for (int k4 = 0; k4 < 16; k4++) {
        float4 w0 = *reinterpret_cast<const float4*>(&Ws[(k4 * 4 + 0) * DD + cx * 4]);
        float4 w1 = *reinterpret_cast<const float4*>(&Ws[(k4 * 4 + 1) * DD + cx * 4]);
        float4 w2 = *reinterpret_cast<const float4*>(&Ws[(k4 * 4 + 2) * DD + cx * 4]);
        float4 w3 = *reinterpret_cast<const float4*>(&Ws[(k4 * 4 + 3) * DD + cx * 4]);
#pragma unroll
        for (int i = 0; i < 16; i++) {
            float4 xv = *reinterpret_cast<const float4*>(&xs[(ry + 16 * i) * XPAD + k4 * 4]);
            acc[i].x = fmaf(w0.x, xv.x, acc[i].x);
            acc[i].y = fmaf(w0.y, xv.x, acc[i].y);
            acc[i].z = fmaf(w0.z, xv.x, acc[i].z);
            acc[i].w = fmaf(w0.w, xv.x, acc[i].w);
            acc[i].x = fmaf(w1.x, xv.y, acc[i].x);
            acc[i].y = fmaf(w1.y, xv.y, acc[i].y);
            acc[i].z = fmaf(w1.z, xv.y, acc[i].z);
            acc[i].w = fmaf(w1.w, xv.y, acc[i].w);
            acc[i].x = fmaf(w2.x, xv.z, acc[i].x);
            acc[i].y = fmaf(w2.y, xv.z, acc[i].y);
            acc[i].z = fmaf(w2.z, xv.z, acc[i].z);
            acc[i].w = fmaf(w2.w, xv.z, acc[i].w);
            acc[i].x = fmaf(w3.x, xv.w, acc[i].x);
            acc[i].y = fmaf(w3.y, xv.w, acc[i].y);
            acc[i].z = fmaf(w3.z, xv.w, acc[i].z);
            acc[i].w = fmaf(w3.w, xv.w, acc[i].w);
        }
    }

    float4 bv = __ldg(reinterpret_cast<const float4*>(b) + cx);
#pragma unroll
    for (int i = 0; i < 16; i++) {
        int grow = row0 + ry + 16 * i;
        if (grow >= n) continue;
        float di = __ldg(dinv + grow);
        float4 h4 = acc[i];
        float4 hs4 = make_float4(h4.x * di, h4.y * di, h4.z * di, h4.w * di);
        float4 ag4 = make_float4(fmaf(hs4.x, di, bv.x), fmaf(hs4.y, di, bv.y),
                                 fmaf(hs4.z, di, bv.z), fmaf(hs4.w, di, bv.w));
        __half2 p0 = __floats2half2_rn(hs4.x, hs4.y);
        __half2 p1 = __floats2half2_rn(hs4.z, hs4.w);
        uint2 packed;
        packed.x = *reinterpret_cast<unsigned int*>(&p0);
        packed.y = *reinterpret_cast<unsigned int*>(&p1);
        *reinterpret_cast<uint2*>(hsh + (size_t)grow * 32 + cx * 2) = packed;
        *reinterpret_cast<float4*>(agg + (size_t)grow * DD + cx * 4) = ag4;
    }
}

// ---------------------------------------------------------------------------
// Gather-by-destination: one warp per node, two edges per warp-step.
// Half-warp h (=lane>>4) processes edges of parity h; lane sub (=lane&15) owns
// columns [4*sub, 4*sub+3] via one uint2 (= 4 fp16) load per edge.
// Final: acc += shfl_xor(acc, 16); half 0 writes  out += acc * dinv[node].
__global__ __launch_bounds__(256)
void k_aggregate(const int* __restrict__ csr, const int* __restrict__ off,
                 const int* __restrict__ cnt, const float* __restrict__ dinv,
                 const __half2* __restrict__ hsh, float* __restrict__ out, int n) {
    int node = blockIdx.x * 8 + (threadIdx.x >> 5);
    int lane = threadIdx.x & 31;
    if (node >= n) return;

    int half = lane >> 4;
    int sub  = lane & 15;
    int beg = off[node];
    int m = cnt[node];
    float nd = dinv[node];

    float4 acc = make_float4(0.f, 0.f, 0.f, 0.f);
    const unsigned FULL = 0xffffffffu;

    int j = 0;
    while (j < m) {
        int rem = m - j;
        int myidx = (lane < rem) ? __ldg(csr + beg + j + lane) : 0;
        int lim = rem < 32 ? rem : 32;
        int t = 0;
        for (; t + 4 <= lim; t += 4) {
            int sa = __shfl_sync(FULL, myidx, t + half);
            int sb = __shfl_sync(FULL, myidx, t + 2 + half);
            uint2 va = __ldg(reinterpret_cast<const uint2*>(hsh + (size_t)sa * 32) + sub);
            uint2 vb = __ldg(reinterpret_cast<const uint2*>(hsh + (size_t)sb * 32) + sub);
            float2 a0 = __half22float2(*reinterpret_cast<__half2*>(&va.x));
            float2 a1 = __half22float2(*reinterpret_cast<__half2*>(&va.y));
            float2 b0 = __half22float2(*reinterpret_cast<__half2*>(&vb.x));
            float2 b1 = __half22float2(*reinterpret_cast<__half2*>(&vb.y));
            acc.x += a0.x + b0.x;
            acc.y += a0.y + b0.y;
            acc.z += a1.x + b1.x;
            acc.w += a1.y + b1.y;
        }
        for (; t < lim; t += 2) {
            int eid = t + half;
            int s = __shfl_sync(FULL, myidx, (eid < lim) ? eid : 0);
            if (eid < lim) {
                uint2 v = __ldg(reinterpret_cast<const uint2*>(hsh + (size_t)s * 32) + sub);
                float2 f0 = __half22float2(*reinterpret_cast<__half2*>(&v.x));
                float2 f1 = __half22float2(*reinterpret_cast<__half2*>(&v.y));
                acc.x += f0.x; acc.y += f0.y; acc.z += f1.x; acc.w += f1.y;
            }
        }
        j += 32;
    }

    acc.x += __shfl_xor_sync(FULL, acc.x, 16);
    acc.y += __shfl_xor_sync(FULL, acc.y, 16);
    acc.z += __shfl_xor_sync(FULL, acc.z, 16);
    acc.w += __shfl_xor_sync(FULL, acc.w, 16);

    if (half == 0) {
        float4* op = reinterpret_cast<float4*>(out + (size_t)node * DD + sub * 4);
        float4 o = *op;
        o.x = fmaf(acc.x, nd, o.x);
        o.y = fmaf(acc.y, nd, o.y);
        o.z = fmaf(acc.z, nd, o.z);
        o.w = fmaf(acc.w, nd, o.w);
        *op = o;
    }
}

// ---------------------------------------------------------------------------
static void* sym_addr(const void* sym) {
    void* p = nullptr;
    cudaGetSymbolAddress(&p, sym);
    return p;
}

extern "C" void kernel_launch(void* const* d_in, const int* in_sizes, int n_in,
                              void* d_out, int out_size) {
    const float* x  = (const float*)d_in[0];
    const float* W1 = (const float*)d_in[1];
    const float* b1 = (const float*)d_in[2];
    const float* W2 = (const float*)d_in[3];
    const float* b2 = (const float*)d_in[4];
    const int*   e0 = (const int*)d_in[5];   // [2, E]: src row then dst row
    const int*   e1 = (const int*)d_in[6];

    const int N = in_sizes[0] / DD;
    const int E = in_sizes[5] / 2;
    const int NB = (N + SCAN_B - 1) / SCAN_B;

    float*  dinv  = (float*)sym_addr(g_dinv);
    int*    cnt   = (int*)sym_addr(g_cnt);
    int*    off   = (int*)sym_addr(g_off);
    int*    cur   = (int*)sym_addr(g_cur);
    int*    bsum  = (int*)sym_addr(g_bsum);
    int*    csr   = (int*)sym_addr(g_csr);
    float*  dinv2 = (float*)sym_addr(g_dinv2);
    int*    cnt2  = (int*)sym_addr(g_cnt2);
    int*    off2  = (int*)sym_addr(g_off2);
    int*    cur2  = (int*)sym_addr(g_cur2);
    int*    bsum2 = (int*)sym_addr(g_bsum2);
    int*    csr2  = (int*)sym_addr(g_csr2);
    __half2* hsh  = (__half2*)sym_addr(g_hsh);
    float*  agg   = (float*)sym_addr(g_agg);
    float*  out   = (float*)d_out;

    const int T = 256;
    int n_grid  = (N + T - 1) / T;
    int e_grid  = (E + T - 1) / T;
    int ag_grid = (N + 7) / 8;
    int gm_grid = (N + 255) / 256;
    size_t gm_smem = (DD * DD + 256 * XPAD) * sizeof(float);

    static cudaStream_t sFill = nullptr, sCsr2 = nullptr;
    static cudaEvent_t evFork, evScan3, evFill0, evCsr2;
    static int init_done = 0;
    if (!init_done) {
        cudaFuncSetAttribute(k_gemm_fused, cudaFuncAttributeMaxDynamicSharedMemorySize,
                             (int)gm_smem);
        cudaStreamCreateWithFlags(&sFill, cudaStreamNonBlocking);
        cudaStreamCreateWithFlags(&sCsr2, cudaStreamNonBlocking);
        cudaEventCreateWithFlags(&evFork, cudaEventDisableTiming);
        cudaEventCreateWithFlags(&evScan3, cudaEventDisableTiming);
        cudaEventCreateWithFlags(&evFill0, cudaEventDisableTiming);
        cudaEventCreateWithFlags(&evCsr2, cudaEventDisableTiming);
        init_done = 1;
    }

    // -------- fork: layer-2 CSR build runs concurrently on sCsr2 --------
    cudaEventRecord(evFork, 0);
    cudaStreamWaitEvent(sCsr2, evFork, 0);
    cudaMemsetAsync(cnt2, 0, N * sizeof(int), sCsr2);
    k_count<<<e_grid, T, 0, sCsr2>>>(e1 + E, cnt2, E);
    k_scan1<<<NB, SCAN_B, 0, sCsr2>>>(cnt2, off2, bsum2, N);
    k_scan2<<<1, 32, 0, sCsr2>>>(bsum2, NB);
    k_scan3<<<n_grid, T, 0, sCsr2>>>(off2, bsum2, cur2, cnt2, dinv2, N);
    k_fill<<<e_grid, T, 0, sCsr2>>>(e1, e1 + E, cur2, csr2, E);
    cudaEventRecord(evCsr2, sCsr2);

    // -------- Layer 1 (main/legacy stream) --------
    cudaMemsetAsync(cnt, 0, N * sizeof(int));
    k_count<<<e_grid, T>>>(e0 + E, cnt, E);
    k_scan1<<<NB, SCAN_B>>>(cnt, off, bsum, N);
    k_scan2<<<1, 32>>>(bsum, NB);
    k_scan3<<<n_grid, T>>>(off, bsum, cur, cnt, dinv, N);
    // fork fill0 so it overlaps gemm1 (both depend only on scan3)
    cudaEventRecord(evScan3, 0);
    cudaStreamWaitEvent(sFill, evScan3, 0);
    k_fill<<<e_grid, T, 0, sFill>>>(e0, e0 + E, cur, csr, E);
    cudaEventRecord(evFill0, sFill);

    k_gemm_fused<<<gm_grid, 256, gm_smem>>>(x, W1, b1, dinv, hsh, agg, N, 0);
    cudaStreamWaitEvent(0, evFill0, 0);
    k_aggregate<<<ag_grid, T>>>(csr, off, cnt, dinv, hsh, agg, N);

    // -------- Layer 2 (join CSR2) --------
    cudaStreamWaitEvent(0, evCsr2, 0);
    k_gemm_fused<<<gm_grid, 256, gm_smem>>>(agg, W2, b2, dinv2, hsh, out, N, 1);  // ReLU fused
    k_aggregate<<<ag_grid, T>>>(csr2, off2, cnt2, dinv2, hsh, out, N);
}